// round 3
// baseline (speedup 1.0000x reference)
#include <cuda_runtime.h>
#include <cstdint>
#include <cstddef>

#define TAME_F  100000.0f
#define TAME2_F 1.0e10f
#define KSTEPS  60          // 8760 = 60 * 146
#define NTHR    32          // one warp per block -> one warp per SM

__device__ __forceinline__ float frsq(float x) {
    float r;
    asm("rsqrt.approx.f32 %0, %1;" : "=f"(r) : "f"(x));
    return r;
}

__device__ __forceinline__ uint32_t smem_u32(const void* p) {
    uint32_t a;
    asm("{ .reg .u64 t; cvta.to.shared.u64 t, %1; cvt.u32.u64 %0, t; }"
        : "=r"(a) : "l"(p));
    return a;
}

// One thread = one system; 32 threads/block, 128 blocks -> 1 warp per SM.
// The sequential scan is issue+latency bound per warp:
//  - external data staged once in smem as float4 rows -> 1 broadcast LDS.128/step
//  - outputs staged via cheap STS into a double-buffered smem ring; each LANE
//    flushes its own rows with per-thread cp.async.bulk groups (384 B each,
//    contiguous in gmem). No __syncthreads, no serial single-thread flush.
__global__ void __launch_bounds__(NTHR, 1)
tithte_kernel(const float* __restrict__ state0,
              const float* __restrict__ params,
              const float* __restrict__ ed,
              const int*   __restrict__ dtp,
              float*       __restrict__ out,
              int B, int T)
{
    extern __shared__ float4 sm4[];           // [0 .. T+1]: padded ed rows
    float* buf = (float*)(sm4 + (T + 2));     // 2 * KSTEPS * 96 floats

    const int tid = threadIdx.x;              // == lane id

    // stage external_data as float4 rows {T_out, heat, solar, 0}, zero-pad 2 rows
    #pragma unroll 4
    for (int r = tid; r < T + 2; r += NTHR) {
        float4 v = make_float4(0.f, 0.f, 0.f, 0.f);
        if (r < T) { v.x = ed[3*r]; v.y = ed[3*r+1]; v.z = ed[3*r+2]; }
        sm4[r] = v;
    }
    __syncthreads();

    const int b = blockIdx.x * NTHR + tid;

    const float dtf = (float)dtp[0];
    const float C1 = params[b*6+0], R1 = params[b*6+1];
    const float C2 = params[b*6+2], R2 = params[b*6+3];
    const float C3 = params[b*6+4], R3 = params[b*6+5];

    const float a1 = dtf / C1, a2 = dtf / C2, a3 = dtf / C3;
    const float iR1 = 1.0f / R1, iR2 = 1.0f / R2, iR3 = 1.0f / R3;

    // x = M*s + c : x1 = dT_in, x2 = dT_heater, x3 = dT_env (pre-tame)
    const float m12 = a1 * iR2, m13 = a1 * iR1, m11 = -(m12 + m13);
    const float m21 = a2 * iR2, m22 = -m21;
    const float m31 = a3 * iR1, k33 = a3 * iR3, m33 = -(m31 + k33);

    float s1 = state0[b*3+0], s2 = state0[b*3+1], s3 = state0[b*3+2];

    // prologue: x(0) from row 0
    float4 row0 = sm4[0];
    float c1 = a1  * row0.z;
    float c2 = a2  * row0.y;
    float c3 = k33 * row0.x;
    float x1 = fmaf(m13, s3, fmaf(m12, s2, fmaf(m11, s1, c1)));
    float x2 = fmaf(m22, s2, fmaf(m21, s1, c2));
    float x3 = fmaf(m33, s3, fmaf(m31, s1, c3));
    float h1 = fmaf(x1, x1, TAME2_F), tx1 = x1 * TAME_F;
    float h2 = fmaf(x2, x2, TAME2_F), tx2 = x2 * TAME_F;
    float h3 = fmaf(x3, x3, TAME2_F), tx3 = x3 * TAME_F;

    float4 nr = sm4[1];   // prefetched row t+1

    const uint32_t buf_u32 = smem_u32(buf);
    char* gbase = (char*)out + (size_t)blockIdx.x * (NTHR * 3 * sizeof(float));
    const size_t grow = (size_t)B * 3 * sizeof(float);   // 49152 B

    int t = 0;
    int phase = 0;
    const int nep = T / KSTEPS;   // 146

    for (int ep = 0; ep < nep; ++ep) {
        float* bp = buf + phase * (KSTEPS * NTHR * 3) + tid * 3;

        #pragma unroll 4
        for (int k = 0; k < KSTEPS; ++k, ++t) {
            const float r1 = frsq(h1);
            const float r2 = frsq(h2);
            const float r3 = frsq(h3);
            s1 = fmaf(tx1, r1, s1);
            s2 = fmaf(tx2, r2, s2);
            s3 = fmaf(tx3, r3, s3);

            bp[0] = s1; bp[1] = s2; bp[2] = s3;
            bp += NTHR * 3;

            c1 = a1  * nr.z;
            c2 = a2  * nr.y;
            c3 = k33 * nr.x;
            nr = sm4[t + 2];            // prefetch row t+2 (zero-padded)

            // accumulate in s'-arrival order: s1 (first rsqrt) innermost,
            // s3 (last rsqrt) outermost
            x1 = fmaf(m13, s3, fmaf(m12, s2, fmaf(m11, s1, c1)));
            x2 = fmaf(m22, s2, fmaf(m21, s1, c2));
            x3 = fmaf(m33, s3, fmaf(m31, s1, c3));

            h1 = fmaf(x1, x1, TAME2_F); tx1 = x1 * TAME_F;
            h2 = fmaf(x2, x2, TAME2_F); tx2 = x2 * TAME_F;
            h3 = fmaf(x3, x3, TAME2_F); tx3 = x3 * TAME_F;
        }

        // per-lane flush of this epoch's buffer: lane L copies rows L, L+32.
        // Each lane has its own bulk group -> fully parallel, warp-local.
        __syncwarp();
        asm volatile("fence.proxy.async.shared::cta;" ::: "memory");
        {
            char* gdst = gbase + (size_t)(t - KSTEPS) * grow;
            uint32_t ssrc = buf_u32 + (uint32_t)phase * (KSTEPS * NTHR * 12);
            for (int r = tid; r < KSTEPS; r += NTHR) {
                asm volatile(
                    "cp.async.bulk.global.shared::cta.bulk_group [%0], [%1], %2;"
                    :: "l"(gdst + (size_t)r * grow),
                       "r"(ssrc + (uint32_t)r * (NTHR * 12)),
                       "n"(NTHR * 12)
                    : "memory");
            }
            asm volatile("cp.async.bulk.commit_group;" ::: "memory");
            // keep only this epoch's group in flight: the group committed in
            // the previous epoch (other buffer) is guaranteed drained.
            asm volatile("cp.async.bulk.wait_group 1;" ::: "memory");
        }
        __syncwarp();
        phase ^= 1;
    }

    asm volatile("cp.async.bulk.wait_group 0;" ::: "memory");
}

extern "C" void kernel_launch(void* const* d_in, const int* in_sizes, int n_in,
                              void* d_out, int out_size) {
    const float* state0 = (const float*)d_in[0];
    const float* params = (const float*)d_in[1];
    const float* ed     = (const float*)d_in[2];
    const int*   dtp    = (const int*)d_in[3];
    float* out = (float*)d_out;

    const int B = in_sizes[0] / 3;   // (B, 3)
    const int T = in_sizes[2] / 3;   // (T, 3)

    const int blocks = B / NTHR;     // 128
    const size_t smem = (size_t)(T + 2) * sizeof(float4)
                      + (size_t)2 * KSTEPS * NTHR * 3 * sizeof(float);

    cudaFuncSetAttribute(tithte_kernel,
                         cudaFuncAttributeMaxDynamicSharedMemorySize, (int)smem);
    tithte_kernel<<<blocks, NTHR, smem>>>(state0, params, ed, dtp, out, B, T);
}

// round 4
// speedup vs baseline: 1.2062x; 1.2062x over previous
#include <cuda_runtime.h>
#include <cstdint>
#include <cstddef>

#define TAME_F  100000.0f
#define TAME2_F 1.0e10f
#define NTHR    32

typedef unsigned long long u64;

__device__ __forceinline__ float frsq(float x) {
    float r;
    asm("rsqrt.approx.f32 %0, %1;" : "=f"(r) : "f"(x));
    return r;
}
__device__ __forceinline__ u64 pk2(float lo, float hi) {
    u64 r;
    asm("mov.b64 %0, {%1, %2};" : "=l"(r) : "f"(lo), "f"(hi));
    return r;
}
__device__ __forceinline__ void upk2(float& lo, float& hi, u64 v) {
    asm("mov.b64 {%0, %1}, %2;" : "=f"(lo), "=f"(hi) : "l"(v));
}
__device__ __forceinline__ u64 fma2(u64 a, u64 b, u64 c) {
    u64 d;
    asm("fma.rn.f32x2 %0, %1, %2, %3;" : "=l"(d) : "l"(a), "l"(b), "l"(c));
    return d;
}
__device__ __forceinline__ u64 mul2(u64 a, u64 b) {
    u64 d;
    asm("mul.rn.f32x2 %0, %1, %2;" : "=l"(d) : "l"(a), "l"(b));
    return d;
}

// Two systems per thread (pair 2i, 2i+1), packed into f32x2 ops.
// 64 blocks x 32 threads -> 1 warp per SM, dedicated SMSP per warp.
// The two independent per-system dependency chains interleave, turning the
// latency-bound scan into an issue-bound one; f32x2 halves the fp issue count.
// Outputs of a pair are 24 contiguous bytes -> 3x STG.64 per iteration.
__global__ void __launch_bounds__(NTHR, 1)
tithte_kernel(const float* __restrict__ state0,
              const float* __restrict__ params,
              const float* __restrict__ ed,
              const int*   __restrict__ dtp,
              float*       __restrict__ out,
              int B, int T)
{
    extern __shared__ float4 sm4[];   // [0 .. T+1] padded ed rows {T_out, heat, solar, 0}

    const int tid = threadIdx.x;

    #pragma unroll 4
    for (int r = tid; r < T + 2; r += NTHR) {
        float4 v = make_float4(0.f, 0.f, 0.f, 0.f);
        if (r < T) { v.x = ed[3*r]; v.y = ed[3*r+1]; v.z = ed[3*r+2]; }
        sm4[r] = v;
    }
    __syncthreads();

    const int gi = blockIdx.x * NTHR + tid;   // pair index
    const float dtf = (float)dtp[0];

    // per-system coefficients for systems a = 2*gi, b = 2*gi+1
    u64 m11p, m12p, m13p, m21p, m22p, m31p, m33p, k33p, a1p, a2p;
    u64 s1, s2, s3;
    {
        float m11s[2], m12s[2], m13s[2], m21s[2], m22s[2], m31s[2], m33s[2], k33s[2], a1s[2], a2s[2];
        float s1s[2], s2s[2], s3s[2];
        #pragma unroll
        for (int j = 0; j < 2; ++j) {
            const int b = 2 * gi + j;
            const float C1 = params[b*6+0], R1 = params[b*6+1];
            const float C2 = params[b*6+2], R2 = params[b*6+3];
            const float C3 = params[b*6+4], R3 = params[b*6+5];
            const float a1 = dtf / C1, a2 = dtf / C2, a3 = dtf / C3;
            const float iR1 = 1.0f / R1, iR2 = 1.0f / R2, iR3 = 1.0f / R3;
            m12s[j] = a1 * iR2; m13s[j] = a1 * iR1; m11s[j] = -(m12s[j] + m13s[j]);
            m21s[j] = a2 * iR2; m22s[j] = -m21s[j];
            m31s[j] = a3 * iR1; k33s[j] = a3 * iR3; m33s[j] = -(m31s[j] + k33s[j]);
            a1s[j] = a1; a2s[j] = a2;
            s1s[j] = state0[b*3+0]; s2s[j] = state0[b*3+1]; s3s[j] = state0[b*3+2];
        }
        m11p = pk2(m11s[0], m11s[1]); m12p = pk2(m12s[0], m12s[1]); m13p = pk2(m13s[0], m13s[1]);
        m21p = pk2(m21s[0], m21s[1]); m22p = pk2(m22s[0], m22s[1]);
        m31p = pk2(m31s[0], m31s[1]); m33p = pk2(m33s[0], m33s[1]); k33p = pk2(k33s[0], k33s[1]);
        a1p = pk2(a1s[0], a1s[1]); a2p = pk2(a2s[0], a2s[1]);
        s1 = pk2(s1s[0], s1s[1]); s2 = pk2(s2s[0], s2s[1]); s3 = pk2(s3s[0], s3s[1]);
    }
    const u64 tame2p = pk2(TAME2_F, TAME2_F);
    const u64 tamep  = pk2(TAME_F,  TAME_F);

    // prologue: x(0), h(0), tx(0) from row 0
    float4 nr = sm4[0];
    u64 c1 = mul2(a1p,  pk2(nr.z, nr.z));
    u64 c2 = mul2(a2p,  pk2(nr.y, nr.y));
    u64 c3 = mul2(k33p, pk2(nr.x, nr.x));
    u64 x1 = fma2(m13p, s3, fma2(m12p, s2, fma2(m11p, s1, c1)));
    u64 x2 = fma2(m22p, s2, fma2(m21p, s1, c2));
    u64 x3 = fma2(m33p, s3, fma2(m31p, s1, c3));
    u64 h1 = fma2(x1, x1, tame2p), tx1 = mul2(x1, tamep);
    u64 h2 = fma2(x2, x2, tame2p), tx2 = mul2(x2, tamep);
    u64 h3 = fma2(x3, x3, tame2p), tx3 = mul2(x3, tamep);

    nr = sm4[1];   // prefetched row t+1

    char* op = (char*)out + (size_t)gi * 24;
    const size_t grow = (size_t)B * 12;

    #pragma unroll 4
    for (int t = 0; t < T; ++t) {
        // tame + state update (chains of the two packed systems hide each other)
        float h1a, h1b, h2a, h2b, h3a, h3b;
        upk2(h1a, h1b, h1);
        upk2(h2a, h2b, h2);
        upk2(h3a, h3b, h3);
        const u64 r1 = pk2(frsq(h1a), frsq(h1b));
        const u64 r2 = pk2(frsq(h2a), frsq(h2b));
        const u64 r3 = pk2(frsq(h3a), frsq(h3b));
        s1 = fma2(tx1, r1, s1);
        s2 = fma2(tx2, r2, s2);
        s3 = fma2(tx3, r3, s3);

        // store pair's 6 contiguous floats: [s1a s2a s3a s1b s2b s3b]
        float s1a, s1b, s2a, s2b, s3a, s3b;
        upk2(s1a, s1b, s1);
        upk2(s2a, s2b, s2);
        upk2(s3a, s3b, s3);
        ((float2*)op)[0] = make_float2(s1a, s2a);
        ((float2*)op)[1] = make_float2(s3a, s1b);
        ((float2*)op)[2] = make_float2(s2b, s3b);
        op += grow;

        // next c from prefetched row; prefetch t+2 (zero-padded)
        c1 = mul2(a1p,  pk2(nr.z, nr.z));
        c2 = mul2(a2p,  pk2(nr.y, nr.y));
        c3 = mul2(k33p, pk2(nr.x, nr.x));
        nr = sm4[t + 2];

        // x(t+1) accumulated in s'-arrival order (s1 first, s3 last)
        x1 = fma2(m13p, s3, fma2(m12p, s2, fma2(m11p, s1, c1)));
        x2 = fma2(m22p, s2, fma2(m21p, s1, c2));
        x3 = fma2(m33p, s3, fma2(m31p, s1, c3));

        h1 = fma2(x1, x1, tame2p); tx1 = mul2(x1, tamep);
        h2 = fma2(x2, x2, tame2p); tx2 = mul2(x2, tamep);
        h3 = fma2(x3, x3, tame2p); tx3 = mul2(x3, tamep);
    }
}

extern "C" void kernel_launch(void* const* d_in, const int* in_sizes, int n_in,
                              void* d_out, int out_size) {
    const float* state0 = (const float*)d_in[0];
    const float* params = (const float*)d_in[1];
    const float* ed     = (const float*)d_in[2];
    const int*   dtp    = (const int*)d_in[3];
    float* out = (float*)d_out;

    const int B = in_sizes[0] / 3;   // (B, 3)
    const int T = in_sizes[2] / 3;   // (T, 3)

    const int pairs  = B / 2;
    const int blocks = pairs / NTHR;   // 64
    const size_t smem = (size_t)(T + 2) * sizeof(float4);

    cudaFuncSetAttribute(tithte_kernel,
                         cudaFuncAttributeMaxDynamicSharedMemorySize, (int)smem);
    tithte_kernel<<<blocks, NTHR, smem>>>(state0, params, ed, dtp, out, B, T);
}

// round 5
// speedup vs baseline: 1.2092x; 1.0025x over previous
#include <cuda_runtime.h>
#include <cstdint>
#include <cstddef>

#define TAME_F  100000.0f
#define TAME2_F 1.0e10f
#define NTHR    32

typedef unsigned long long u64;

__device__ __forceinline__ float frsq(float x) {
    float r;
    asm("rsqrt.approx.f32 %0, %1;" : "=f"(r) : "f"(x));
    return r;
}
__device__ __forceinline__ u64 pk2(float lo, float hi) {
    u64 r;
    asm("mov.b64 %0, {%1, %2};" : "=l"(r) : "f"(lo), "f"(hi));
    return r;
}
__device__ __forceinline__ void upk2(float& lo, float& hi, u64 v) {
    asm("mov.b64 {%0, %1}, %2;" : "=f"(lo), "=f"(hi) : "l"(v));
}
__device__ __forceinline__ u64 fma2(u64 a, u64 b, u64 c) {
    u64 d;
    asm("fma.rn.f32x2 %0, %1, %2, %3;" : "=l"(d) : "l"(a), "l"(b), "l"(c));
    return d;
}
__device__ __forceinline__ u64 mul2(u64 a, u64 b) {
    u64 d;
    asm("mul.rn.f32x2 %0, %1, %2;" : "=l"(d) : "l"(a), "l"(b));
    return d;
}

// 2 systems/thread (2i, 2i+1) with f32x2 math; 64 blocks x 32 threads ->
// 1 warp/SM, private SMSP. Scalar<->packed crossings confined to the
// MUFU.RSQ island (unpack h, pack r); store unpacks and c-broadcast packs
// run on the (idle) ALU pipe off the dependency chain.
__global__ void __launch_bounds__(NTHR, 1)
tithte_kernel(const float* __restrict__ state0,
              const float* __restrict__ params,
              const float* __restrict__ ed,
              const int*   __restrict__ dtp,
              float*       __restrict__ out,
              int B, int T)
{
    extern __shared__ float4 sm4[];   // [0..T+1] rows {T_out, heat, solar, 0}

    const int tid = threadIdx.x;

    #pragma unroll 4
    for (int r = tid; r < T + 2; r += NTHR) {
        float4 v = make_float4(0.f, 0.f, 0.f, 0.f);
        if (r < T) { v.x = ed[3*r]; v.y = ed[3*r+1]; v.z = ed[3*r+2]; }
        sm4[r] = v;
    }
    __syncthreads();

    const int gi = blockIdx.x * NTHR + tid;   // pair index
    const float dtf = (float)dtp[0];

    u64 m11p, m12p, m13p, m21p, m22p, m31p, m33p, k33p, a1p, a2p;
    u64 s1, s2, s3;
    {
        float v[10][2], ss[3][2];
        #pragma unroll
        for (int j = 0; j < 2; ++j) {
            const int b = 2 * gi + j;
            const float C1 = params[b*6+0], R1 = params[b*6+1];
            const float C2 = params[b*6+2], R2 = params[b*6+3];
            const float C3 = params[b*6+4], R3 = params[b*6+5];
            const float a1 = dtf / C1, a2 = dtf / C2, a3 = dtf / C3;
            const float iR1 = 1.0f / R1, iR2 = 1.0f / R2, iR3 = 1.0f / R3;
            const float m12 = a1 * iR2, m13 = a1 * iR1;
            const float m21 = a2 * iR2;
            const float m31 = a3 * iR1, k33 = a3 * iR3;
            v[0][j] = -(m12 + m13); v[1][j] = m12; v[2][j] = m13;
            v[3][j] = m21;          v[4][j] = -m21;
            v[5][j] = m31;          v[6][j] = -(m31 + k33); v[7][j] = k33;
            v[8][j] = a1;           v[9][j] = a2;
            ss[0][j] = state0[b*3+0]; ss[1][j] = state0[b*3+1]; ss[2][j] = state0[b*3+2];
        }
        m11p = pk2(v[0][0], v[0][1]); m12p = pk2(v[1][0], v[1][1]); m13p = pk2(v[2][0], v[2][1]);
        m21p = pk2(v[3][0], v[3][1]); m22p = pk2(v[4][0], v[4][1]);
        m31p = pk2(v[5][0], v[5][1]); m33p = pk2(v[6][0], v[6][1]); k33p = pk2(v[7][0], v[7][1]);
        a1p  = pk2(v[8][0], v[8][1]); a2p  = pk2(v[9][0], v[9][1]);
        s1 = pk2(ss[0][0], ss[0][1]); s2 = pk2(ss[1][0], ss[1][1]); s3 = pk2(ss[2][0], ss[2][1]);
    }
    const u64 tame2p = pk2(TAME2_F, TAME2_F);
    const u64 tamep  = pk2(TAME_F,  TAME_F);

    // prologue from row 0
    float4 nr = sm4[0];
    u64 c1 = mul2(a1p,  pk2(nr.z, nr.z));
    u64 c2 = mul2(a2p,  pk2(nr.y, nr.y));
    u64 c3 = mul2(k33p, pk2(nr.x, nr.x));
    u64 x1 = fma2(m13p, s3, fma2(m12p, s2, fma2(m11p, s1, c1)));
    u64 x2 = fma2(m22p, s2, fma2(m21p, s1, c2));
    u64 x3 = fma2(m33p, s3, fma2(m31p, s1, c3));
    u64 h1 = fma2(x1, x1, tame2p), tx1 = mul2(x1, tamep);
    u64 h2 = fma2(x2, x2, tame2p), tx2 = mul2(x2, tamep);
    u64 h3 = fma2(x3, x3, tame2p), tx3 = mul2(x3, tamep);

    nr = sm4[1];

    char* op = (char*)out + (size_t)gi * 24;
    const size_t grow = (size_t)B * 12;

    #pragma unroll 4
    for (int t = 0; t < T; ++t) {
        // --- MUFU island: the ONLY on-chain scalar<->packed crossings ---
        float h1a, h1b, h2a, h2b, h3a, h3b;
        upk2(h1a, h1b, h1);
        upk2(h2a, h2b, h2);
        upk2(h3a, h3b, h3);
        const float r1a = frsq(h1a);   // r1 first: s1' gates every x(t+1)
        const float r1b = frsq(h1b);
        const float r2a = frsq(h2a);
        const float r2b = frsq(h2b);
        const float r3a = frsq(h3a);
        const float r3b = frsq(h3b);
        s1 = fma2(tx1, pk2(r1a, r1b), s1);
        s2 = fma2(tx2, pk2(r2a, r2b), s2);
        s3 = fma2(tx3, pk2(r3a, r3b), s3);

        // store (off-chain): [s1a s2a s3a | s1b s2b s3b]
        {
            float s1a, s1b, s2a, s2b, s3a, s3b;
            upk2(s1a, s1b, s1);
            upk2(s2a, s2b, s2);
            upk2(s3a, s3b, s3);
            ((float2*)op)[0] = make_float2(s1a, s2a);
            ((float2*)op)[1] = make_float2(s3a, s1b);
            ((float2*)op)[2] = make_float2(s2b, s3b);
            op += grow;
        }

        // c(t+1) from prefetched row (broadcast packs: ALU pipe, off-chain)
        c1 = mul2(a1p,  pk2(nr.z, nr.z));
        c2 = mul2(a2p,  pk2(nr.y, nr.y));
        c3 = mul2(k33p, pk2(nr.x, nr.x));
        nr = sm4[t + 2];               // prefetch t+2 (zero-padded)

        // x(t+1): s1 innermost (ready first), s3 outermost (ready last)
        x1 = fma2(m13p, s3, fma2(m12p, s2, fma2(m11p, s1, c1)));
        x2 = fma2(m22p, s2, fma2(m21p, s1, c2));
        x3 = fma2(m33p, s3, fma2(m31p, s1, c3));

        h1 = fma2(x1, x1, tame2p); tx1 = mul2(x1, tamep);
        h2 = fma2(x2, x2, tame2p); tx2 = mul2(x2, tamep);
        h3 = fma2(x3, x3, tame2p); tx3 = mul2(x3, tamep);
    }
}

extern "C" void kernel_launch(void* const* d_in, const int* in_sizes, int n_in,
                              void* d_out, int out_size) {
    const float* state0 = (const float*)d_in[0];
    const float* params = (const float*)d_in[1];
    const float* ed     = (const float*)d_in[2];
    const int*   dtp    = (const int*)d_in[3];
    float* out = (float*)d_out;

    const int B = in_sizes[0] / 3;   // (B, 3)
    const int T = in_sizes[2] / 3;   // (T, 3)

    const int blocks = (B / 2) / NTHR;   // 64
    const size_t smem = (size_t)(T + 2) * sizeof(float4);

    cudaFuncSetAttribute(tithte_kernel,
                         cudaFuncAttributeMaxDynamicSharedMemorySize, (int)smem);
    tithte_kernel<<<blocks, NTHR, smem>>>(state0, params, ed, dtp, out, B, T);
}

// round 6
// speedup vs baseline: 1.6736x; 1.3840x over previous
#include <cuda_runtime.h>
#include <cstdint>
#include <cstddef>

#define TAME_F  100000.0f
#define TAME2_F 1.0e10f
#define NTHR    128

__device__ __forceinline__ float frsq(float x) {
    float r;
    asm("rsqrt.approx.f32 %0, %1;" : "=f"(r) : "f"(x));
    return r;
}

// k=1: one thread = one system, 32 blocks x 128 threads -> 128 warps on 128
// distinct SMSPs (the only config whose fma floor, 36 cyc/step, is below the
// measured 79). Single-warp in-order issue means the MUFU.RSQ waits are only
// hidden by chain-independent work placed BETWEEN the rsqrt issues and their
// consumers: we defer the trajectory stores by one step and slot them (plus
// the c-muls and smem prefetch) into that window.
__global__ void __launch_bounds__(NTHR, 1)
tithte_kernel(const float* __restrict__ state0,
              const float* __restrict__ params,
              const float* __restrict__ ed,
              const int*   __restrict__ dtp,
              float*       __restrict__ out,
              int B, int T)
{
    extern __shared__ float4 sm4[];   // [0..T+1] rows {T_out, heat, solar, 0}

    const int tid = threadIdx.x;

    #pragma unroll 4
    for (int r = tid; r < T + 2; r += NTHR) {
        float4 v = make_float4(0.f, 0.f, 0.f, 0.f);
        if (r < T) { v.x = ed[3*r]; v.y = ed[3*r+1]; v.z = ed[3*r+2]; }
        sm4[r] = v;
    }
    __syncthreads();

    const int b = blockIdx.x * NTHR + tid;

    const float dtf = (float)dtp[0];
    const float C1 = params[b*6+0], R1 = params[b*6+1];
    const float C2 = params[b*6+2], R2 = params[b*6+3];
    const float C3 = params[b*6+4], R3 = params[b*6+5];

    const float a1 = dtf / C1, a2 = dtf / C2, a3 = dtf / C3;
    const float iR1 = 1.0f / R1, iR2 = 1.0f / R2, iR3 = 1.0f / R3;

    const float m12 = a1 * iR2, m13 = a1 * iR1, m11 = -(m12 + m13);
    const float m21 = a2 * iR2, m22 = -m21;
    const float m31 = a3 * iR1, k33 = a3 * iR3, m33 = -(m31 + k33);

    float s1 = state0[b*3+0], s2 = state0[b*3+1], s3 = state0[b*3+2];

    // prologue: x(0), h(0), tx(0) from row 0
    float4 row0 = sm4[0];
    float c1 = a1  * row0.z;
    float c2 = a2  * row0.y;
    float c3 = k33 * row0.x;
    float x1 = fmaf(m13, s3, fmaf(m12, s2, fmaf(m11, s1, c1)));
    float x2 = fmaf(m22, s2, fmaf(m21, s1, c2));
    float x3 = fmaf(m33, s3, fmaf(m31, s1, c3));
    float h1 = fmaf(x1, x1, TAME2_F), tx1 = x1 * TAME_F;
    float h2 = fmaf(x2, x2, TAME2_F), tx2 = x2 * TAME_F;
    float h3 = fmaf(x3, x3, TAME2_F), tx3 = x3 * TAME_F;

    float4 nr = sm4[1];               // prefetched row t+1

    float* op = out + (size_t)b * 3;  // row 0 slot for this system
    const size_t grow = (size_t)B * 3;

    // p* = s(t-1), stored during step t inside the MUFU-wait window.
    // First iteration has no previous row; predicate the store on t>0 is
    // avoided by storing s(0)'s predecessor into row 0's slot then
    // overwriting: instead we simply peel nothing and write row t-1 at
    // iteration t, with iteration 0 skipped via pointer trick: start one row
    // BELOW and let the first three stores write garbage into... not allowed.
    // Cleanest: peel iteration 0 manually.

    // ---- peeled iteration 0 (no deferred store yet) ----
    {
        const float r1 = frsq(h1);
        const float r2 = frsq(h2);
        const float r3 = frsq(h3);
        c1 = a1  * nr.z;
        c2 = a2  * nr.y;
        c3 = k33 * nr.x;
        nr = sm4[2];
        s1 = fmaf(tx1, r1, s1);
        s2 = fmaf(tx2, r2, s2);
        s3 = fmaf(tx3, r3, s3);
        x1 = fmaf(m13, s3, fmaf(m12, s2, fmaf(m11, s1, c1)));
        x2 = fmaf(m22, s2, fmaf(m21, s1, c2));
        x3 = fmaf(m33, s3, fmaf(m31, s1, c3));
        h1 = fmaf(x1, x1, TAME2_F); tx1 = x1 * TAME_F;
        h2 = fmaf(x2, x2, TAME2_F); tx2 = x2 * TAME_F;
        h3 = fmaf(x3, x3, TAME2_F); tx3 = x3 * TAME_F;
    }

    // steady state: iterations t = 1..T-1; store s(t-1) (currently in s*)
    // while step t's rsqrt chain is in flight.
    float p1 = s1, p2 = s2, p3 = s3;

    #pragma unroll 8
    for (int t = 1; t < T; ++t) {
        // issue the three rsqrts first (r1 first: s1' gates every x)
        const float r1 = frsq(h1);
        const float r2 = frsq(h2);
        const float r3 = frsq(h3);

        // ---- filler window: chain-independent work ----
        op[0] = p1; op[1] = p2; op[2] = p3;   // store s(t-1)
        op += grow;
        c1 = a1  * nr.z;                      // c(t+1)
        c2 = a2  * nr.y;
        c3 = k33 * nr.x;
        nr = sm4[t + 2];                      // prefetch row t+2 (zero-padded)

        // ---- chain consumers ----
        s1 = fmaf(tx1, r1, s1);
        s2 = fmaf(tx2, r2, s2);
        s3 = fmaf(tx3, r3, s3);
        p1 = s1; p2 = s2; p3 = s3;            // renamed away by ptxas

        x1 = fmaf(m13, s3, fmaf(m12, s2, fmaf(m11, s1, c1)));
        x2 = fmaf(m22, s2, fmaf(m21, s1, c2));
        x3 = fmaf(m33, s3, fmaf(m31, s1, c3));

        h1 = fmaf(x1, x1, TAME2_F); tx1 = x1 * TAME_F;
        h2 = fmaf(x2, x2, TAME2_F); tx2 = x2 * TAME_F;
        h3 = fmaf(x3, x3, TAME2_F); tx3 = x3 * TAME_F;
    }

    // final row T-1
    op[0] = p1; op[1] = p2; op[2] = p3;
}

extern "C" void kernel_launch(void* const* d_in, const int* in_sizes, int n_in,
                              void* d_out, int out_size) {
    const float* state0 = (const float*)d_in[0];
    const float* params = (const float*)d_in[1];
    const float* ed     = (const float*)d_in[2];
    const int*   dtp    = (const int*)d_in[3];
    float* out = (float*)d_out;

    const int B = in_sizes[0] / 3;   // (B, 3)
    const int T = in_sizes[2] / 3;   // (T, 3)

    const int blocks = B / NTHR;     // 32
    const size_t smem = (size_t)(T + 2) * sizeof(float4);

    cudaFuncSetAttribute(tithte_kernel,
                         cudaFuncAttributeMaxDynamicSharedMemorySize, (int)smem);
    tithte_kernel<<<blocks, NTHR, smem>>>(state0, params, ed, dtp, out, B, T);
}